// round 11
// baseline (speedup 1.0000x reference)
#include <cuda_runtime.h>
#include <cstdint>

// BsplineEncoding: x[1e6,3] -> out[1e6,195]. Per (point,dim): [x, 64 bins],
// only 4 bins nonzero; all 195M floats must be written => pure 780MB write
// stream. Empirical ceiling on this chip: ~6.5-6.9 TB/s (write-only HBM
// efficiency), reached by the smem-tile + TMA-drain family.
//
// Round history:
//  R1 per-output-element compute: 445us (issue-bound).
//  R3 32pt tile + STG drain: 117.4us, DRAM 79.2%.
//  R4 TMA drain: neutral (BW path-independent).
//  R5 64pt tile + 2x TMA store: 115.2us, DRAM 81.7%  <-- best
//  R7 persistent double-buffered: 137us REGRESSION (lost CTA overlap).
//  R8 STG + 512thr: 120.9us REGRESSION.
//  R9 LDG hoist + 4x TMA: neutral.
//
// R10: scale the one trend that paid off — fewer, larger tiles. 80 pts/blk
// (62.4KB smem, 3 CTAs/SM, 12500 blocks, -20% per-tile fixed costs). All
// other choices = R5's proven config.

static constexpr float SCALE    = 30.5f;            // (K-DEG)/(MAX-MIN) = 61/2
static constexpr float CLAMP_HI = 61.0f - 1e-6f;    // K - DEG - EPS
static constexpr int   PTS_PER_BLK = 80;            // 1e6 % 80 == 0, %4 == 0
static constexpr int   TILE_FLOATS = PTS_PER_BLK * 195;   // 15600
static constexpr int   TILE_BYTES  = TILE_FLOATS * 4;     // 62400
static constexpr int   HALF_BYTES  = TILE_BYTES / 2;      // 31200 (16B mult)
static constexpr int   HALF_FLOATS = TILE_FLOATS / 2;     // 7800
static constexpr int   TILE_VEC4   = TILE_FLOATS / 4;     // 3900
static constexpr int   THREADS     = 256;
static constexpr int   NWORK       = PTS_PER_BLK * 3;     // 240 workers

__device__ __forceinline__ uint32_t smem_u32(const void* p) {
    uint32_t a;
    asm("{ .reg .u64 t; cvta.to.shared.u64 t, %1; cvt.u32.u64 %0, t; }"
        : "=r"(a) : "l"(p));
    return a;
}

__global__ __launch_bounds__(THREADS)
void bspline_enc_kernel(const float* __restrict__ xin,
                        float* __restrict__ out)
{
    extern __shared__ __align__(16) float tile[];
    const int tid = threadIdx.x;

    // Hoisted input load; latency hides under the zero phase.
    float xv = 0.0f;
    if (tid < NWORK)
        xv = __ldg(xin + (size_t)blockIdx.x * NWORK + tid);

    // Phase 1: zero the tile (float4 stores, conflict-free).
    float4 z4 = make_float4(0.f, 0.f, 0.f, 0.f);
    float4* t4 = reinterpret_cast<float4*>(tile);
#pragma unroll
    for (int i = tid; i < TILE_VEC4; i += THREADS)
        t4[i] = z4;
    __syncthreads();

    // Phase 2: 240 workers, one per (point, dim).
    if (tid < NWORK) {
        const int p = tid / 3;
        const int d = tid - p * 3;

        float xs = fminf(fmaxf((xv + 1.0f) * SCALE, 0.0f), CLAMP_HI);
        float fi = floorf(xs);
        int  idx = (int)fi;
        float u  = xs - fi;
        float u2 = u * u;
        float u3 = u2 * u;
        float om = 1.0f - u;
        float c0 = om * om * om * (1.0f / 6.0f);
        float c1 = (3.0f * u3 - 6.0f * u2 + 4.0f) * (1.0f / 6.0f);
        float c2 = (-3.0f * u3 + 3.0f * u2 + 3.0f * u + 1.0f) * (1.0f / 6.0f);
        float c3 = u3 * (1.0f / 6.0f);

        float* dst = tile + p * 195 + d * 65;
        dst[0]       = xv;
        dst[1 + idx] = c0;
        dst[2 + idx] = c1;
        dst[3 + idx] = c2;
        dst[4 + idx] = c3;
    }
    __syncthreads();

    // Phase 3: two bulk-async (TMA) stores, one commit group, exit wait.
    if (tid == 0) {
        asm volatile("fence.proxy.async.shared::cta;" ::: "memory");
        float* gdst = out + (size_t)blockIdx.x * TILE_FLOATS;
        uint32_t src = smem_u32(tile);
        asm volatile(
            "cp.async.bulk.global.shared::cta.bulk_group [%0], [%1], %2;"
            :: "l"(gdst), "r"(src), "n"(HALF_BYTES) : "memory");
        asm volatile(
            "cp.async.bulk.global.shared::cta.bulk_group [%0], [%1], %2;"
            :: "l"(gdst + HALF_FLOATS), "r"(src + HALF_BYTES), "n"(HALF_BYTES)
            : "memory");
        asm volatile("cp.async.bulk.commit_group;" ::: "memory");
        // smem dies at block exit; bulk reads must finish first.
        asm volatile("cp.async.bulk.wait_group 0;" ::: "memory");
    }
}

extern "C" void kernel_launch(void* const* d_in, const int* in_sizes, int n_in,
                              void* d_out, int out_size)
{
    const float* x = (const float*)d_in[0];
    float* out = (float*)d_out;

    static bool attr_set = false;
    if (!attr_set) {
        cudaFuncSetAttribute(bspline_enc_kernel,
                             cudaFuncAttributeMaxDynamicSharedMemorySize,
                             TILE_BYTES);
        attr_set = true;
    }

    int n_points = out_size / 195;
    int blocks   = n_points / PTS_PER_BLK;   // 12500 for N = 1e6
    bspline_enc_kernel<<<blocks, THREADS, TILE_BYTES>>>(x, out);
}

// round 13
// speedup vs baseline: 1.0801x; 1.0801x over previous
#include <cuda_runtime.h>
#include <cstdint>

// BsplineEncoding: x[1e6,3] -> out[1e6,195]. Per (point,dim): [x, 64 bins],
// only 4 bins nonzero; all 195M floats written => pure 780MB write stream.
// Established roofline: ~6.5 TB/s effective (81% of 8TB/s spec).
//
// Round history:
//  R1 per-element: 445us (issue-bound).  R3 32pt+STG+256t: 117.4us.
//  R4 TMA: neutral.  R5 64pt+2xTMA+256t: 115.2us <-- best wall.
//  R7 persistent: 137us REGR.  R8 64pt+STG+512t: 120.9us REGR.
//  R9/R10: neutral.  R11 TMA l2::cache_hint: unsupported by ptxas.
//
// R12: the untested drain cell — 64pt + 256t + STG.128 with .cs streaming
// hint (__stcs = evict-first writes, the R11 mechanism via a supported
// path). Also removes the block-exit TMA wait: blocks retire at store issue.

static constexpr float SCALE    = 30.5f;            // (K-DEG)/(MAX-MIN) = 61/2
static constexpr float CLAMP_HI = 61.0f - 1e-6f;    // K - DEG - EPS
static constexpr int   PTS_PER_BLK = 64;
static constexpr int   TILE_FLOATS = PTS_PER_BLK * 195;   // 12480
static constexpr int   TILE_VEC4   = TILE_FLOATS / 4;     // 3120
static constexpr int   THREADS     = 256;
static constexpr int   NWORK       = PTS_PER_BLK * 3;     // 192 workers

__global__ __launch_bounds__(THREADS)
void bspline_enc_kernel(const float* __restrict__ xin,
                        float* __restrict__ out)
{
    __shared__ __align__(16) float tile[TILE_FLOATS];
    const int tid = threadIdx.x;

    // Hoisted input load; latency hides under the zero phase.
    float xv = 0.0f;
    if (tid < NWORK)
        xv = __ldg(xin + (size_t)blockIdx.x * NWORK + tid);

    // Phase 1: zero the tile (float4 stores, conflict-free).
    float4 z4 = make_float4(0.f, 0.f, 0.f, 0.f);
    float4* t4 = reinterpret_cast<float4*>(tile);
#pragma unroll
    for (int i = tid; i < TILE_VEC4; i += THREADS)
        t4[i] = z4;
    __syncthreads();

    // Phase 2: 192 workers, one per (point, dim).
    if (tid < NWORK) {
        const int p = tid / 3;
        const int d = tid - p * 3;

        float xs = fminf(fmaxf((xv + 1.0f) * SCALE, 0.0f), CLAMP_HI);
        float fi = floorf(xs);
        int  idx = (int)fi;
        float u  = xs - fi;
        float u2 = u * u;
        float u3 = u2 * u;
        float om = 1.0f - u;
        float c0 = om * om * om * (1.0f / 6.0f);
        float c1 = (3.0f * u3 - 6.0f * u2 + 4.0f) * (1.0f / 6.0f);
        float c2 = (-3.0f * u3 + 3.0f * u2 + 3.0f * u + 1.0f) * (1.0f / 6.0f);
        float c3 = u3 * (1.0f / 6.0f);

        float* dst = tile + p * 195 + d * 65;
        dst[0]       = xv;
        dst[1 + idx] = c0;
        dst[2 + idx] = c1;
        dst[3 + idx] = c2;
        dst[4 + idx] = c3;
    }
    __syncthreads();

    // Phase 3: streaming (evict-first) float4 drain. Fire-and-forget —
    // block retires at store issue, keeping the block pipeline deep.
    float4* o4 = reinterpret_cast<float4*>(out) + (size_t)blockIdx.x * TILE_VEC4;
#pragma unroll
    for (int i = tid; i < TILE_VEC4; i += THREADS)
        __stcs(o4 + i, t4[i]);
}

extern "C" void kernel_launch(void* const* d_in, const int* in_sizes, int n_in,
                              void* d_out, int out_size)
{
    const float* x = (const float*)d_in[0];
    float* out = (float*)d_out;

    int n_points = out_size / 195;
    int blocks   = n_points / PTS_PER_BLK;   // 15625 for N = 1e6
    bspline_enc_kernel<<<blocks, THREADS>>>(x, out);
}